// round 16
// baseline (speedup 1.0000x reference)
#include <cuda_runtime.h>
#include <cstdint>

// Problem constants
#define BB   16
#define CIN  8
#define COUT 32
#define HH   64
#define WW   64
#define K2   9
#define NC   8          // spline coefficients per feature
#define NF   9          // features per cin: silu + 8 spline bases
#define TILE 8
#define NTILES 64       // 8x8 grid of 8x8 tiles
#define THREADS 128

#define FR    10                       // halo rows
#define FCR   10                       // real halo cols
#define FCP   12                       // padded col stride (conflict-free)
#define FPIX_S (FR * FCP)              // 120 floats per plane (stored)
#define FPIX_R (FR * FCR)              // 100 real pixels
#define SF_FLOATS (NF * FPIX_S)        // 1080
#define WCHUNK   (NF * K2 * COUT)      // 2592 floats per cin

// Fused weights (tiny kernel A). Layout gw[c][f][tap][oc], oc fastest.
__device__ float g_fused[CIN * WCHUNK];

__device__ __forceinline__ float silu_f(float x) {
    return x / (1.0f + __expf(-x));
}

// Packed f32x2 FMA: one issue slot, two fp32 FMAs, bit-identical rounding.
__device__ __forceinline__ void ffma2(unsigned long long& d,
                                      unsigned long long a,
                                      unsigned long long b) {
    asm("fma.rn.f32x2 %0, %1, %2, %0;" : "+l"(d) : "l"(a), "l"(b));
}

__device__ __forceinline__ unsigned long long pack2(float v) {
    unsigned long long p;
    asm("mov.b64 %0, {%1, %1};" : "=l"(p) : "f"(v));
    return p;
}

__device__ __forceinline__ void unpack2(unsigned long long p, float& lo, float& hi) {
    asm("mov.b64 {%0, %1}, %2;" : "=f"(lo), "=f"(hi) : "l"(p));
}

__device__ __forceinline__ void cp_async16(uint32_t saddr, const void* gptr) {
    asm volatile("cp.async.cg.shared.global [%0], [%1], 16;"
                 :: "r"(saddr), "l"(gptr));
}

// De Boor-Cox recursion, degree 3, uniform knots t[j] = (j-3)*0.4 - 1.0.
// Uniform knots => denominators are exactly k*h; divisions replaced by
// compile-time reciprocal multiplies (deviation ~1e-7, tolerance 1e-3).
__device__ __forceinline__ void bspline8(float x, float* __restrict__ out) {
    float t[12];
    #pragma unroll
    for (int j = 0; j < 12; ++j) t[j] = (float)(j - 3) * 0.4f - 1.0f;

    float b[11];
    #pragma unroll
    for (int j = 0; j < 11; ++j)
        b[j] = (x >= t[j] && x < t[j + 1]) ? 1.0f : 0.0f;

    #pragma unroll
    for (int k = 1; k <= 3; ++k) {
        const float inv = 1.0f / (0.4f * (float)k);
        #pragma unroll
        for (int j = 0; j < 10; ++j) {
            if (j < 11 - k) {
                b[j] = (x - t[j]) * inv * b[j]
                     + (t[j + k + 1] - x) * inv * b[j + 1];
            }
        }
    }
    #pragma unroll
    for (int s = 0; s < NC; ++s) out[s] = b[s];
}

// ---- Kernel A: fuse base/spline weights into g_fused (tiny) ----
__global__ void kan_fuse_kernel(const float* __restrict__ base_w,
                                const float* __restrict__ spline_w,
                                const float* __restrict__ spline_s)
{
    const int i = blockIdx.x * blockDim.x + threadIdx.x;
    if (i >= CIN * WCHUNK) return;
    const int oc  = i & (COUT - 1);
    const int tap = (i / COUT) % K2;
    const int f   = (i / (COUT * K2)) % NF;
    const int c   = i / WCHUNK;
    const int widx = (oc * CIN + c) * K2 + tap;
    float w;
    if (f == 0) w = base_w[widx];
    else        w = spline_w[widx * NC + (f - 1)] * spline_s[widx];
    g_fused[i] = w;
}

// ---- Kernel B: main conv with in-CTA feature generation.
// 1024 CTAs x 128 threads -> 7 CTAs/SM, ONE balanced wave.
// Thread: ocg = tid >> 4 (8 groups of 4 oc); pxb = tid & 15 -> 2x2 pixel
// block: pr = pxb>>2 (rows 2pr,2pr+1), pc = pxb&3 (cols 2pc,2pc+1).
// Per tap: 1 LDS.128 (broadcast per half-warp) feeds 8 FFMA2 (4 px x 4 oc).
// Features computed in-CTA one cin ahead (double buffer, 1 barrier/cin);
// weights staged via cp.async one cin ahead. featgen latency of one CTA
// overlaps the other 6 CTAs' FMA streams.
__global__ void __launch_bounds__(THREADS, 7)
kan_conv_kernel(const float* __restrict__ x,
                float* __restrict__ out)
{
    __shared__ __align__(16) float sF[2][SF_FLOATS];
    __shared__ __align__(16) float sW[2][WCHUNK];

    const int tid  = threadIdx.x;
    const int tile = blockIdx.x;      // 0..63
    const int b    = blockIdx.y;      // 0..15
    const int th0  = (tile >> 3) * TILE;
    const int tw0  = (tile & 7) * TILE;

    const int ocg = tid >> 4;         // 0..7
    const int pxb = tid & 15;
    const int pr  = pxb >> 2;         // 0..3 -> rows 2pr, 2pr+1
    const int pc  = pxb & 3;          // 0..3 -> cols 2pc, 2pc+1

    // featgen thread mapping (first 100 threads)
    const int fhr = tid / FCR;
    const int fhc = tid % FCR;
    const bool fgen = (tid < FPIX_R);
    const int fgh = th0 + fhr - 1;
    const int fgw = tw0 + fhc - 1;
    const bool finb = fgen && fgh >= 0 && fgh < HH && fgw >= 0 && fgw < WW;

    auto featgen = [&](int c, float* dst) {
        if (fgen) {
            float v = 0.0f;
            if (finb)
                v = x[(b * CIN + c) * (HH * WW) + fgh * WW + fgw];
            float bs[NC];
            bspline8(v, bs);
            const int o = fhr * FCP + fhc;
            dst[o] = silu_f(v);
            #pragma unroll
            for (int s = 0; s < NC; ++s)
                dst[(s + 1) * FPIX_S + o] = bs[s];
        }
    };

    auto prefetch_w = [&](int c, int bufIdx) {
        const float4* wsrc =
            reinterpret_cast<const float4*>(g_fused + c * WCHUNK);
        const uint32_t wdst =
            (uint32_t)__cvta_generic_to_shared(&sW[bufIdx][0]);
        #pragma unroll
        for (int k = 0; k < 6; ++k) {
            const int i = tid + k * THREADS;
            if (i < WCHUNK / 4)                 // 648
                cp_async16(wdst + i * 16, wsrc + i);
        }
        asm volatile("cp.async.commit_group;");
    };

    // Accumulators: 4 px x 4 oc = 16 floats as 8 packed f32x2.
    unsigned long long acc[4][2];
    #pragma unroll
    for (int p = 0; p < 4; ++p) { acc[p][0] = 0ULL; acc[p][1] = 0ULL; }

    // ---- prologue: cin 0 ----
    prefetch_w(0, 0);
    featgen(0, sF[0]);

    for (int c = 0; c < CIN; ++c) {
        const int buf = c & 1;

        if (c < CIN - 1) {
            prefetch_w(c + 1, 1 - buf);
            asm volatile("cp.async.wait_group 1;");   // weights(c) arrived
        } else {
            asm volatile("cp.async.wait_group 0;");
        }
        __syncthreads();   // sF[buf]/sW[buf] ready; conv(c-1) done with buf^1

        if (c < CIN - 1)
            featgen(c + 1, sF[1 - buf]);

        const float* __restrict__ sFb = sF[buf];
        const float* __restrict__ sWb = sW[buf];

        #pragma unroll 3
        for (int f = 0; f < NF; ++f) {
            const float* fpl = sFb + f * FPIX_S;

            // rolling window rows: rw[0] = row (2pr+dh), rw[1] = next row
            unsigned long long rw[2][4];
            #pragma unroll
            for (int k = 0; k < 2; ++k) {
                const int base = (2 * pr + k) * FCP + 2 * pc;
                #pragma unroll
                for (int wc = 0; wc < 4; ++wc)
                    rw[k][wc] = pack2(fpl[base + wc]);
            }

            const float* wbase = sWb + (f * K2) * COUT + ocg * 4;

            #pragma unroll
            for (int dh = 0; dh < 3; ++dh) {
                #pragma unroll
                for (int dw = 0; dw < 3; ++dw) {
                    const int tap = dh * 3 + dw;
                    const ulonglong2 w = *reinterpret_cast<const ulonglong2*>(
                        wbase + tap * COUT);
                    #pragma unroll
                    for (int i = 0; i < 2; ++i) {
                        #pragma unroll
                        for (int j = 0; j < 2; ++j) {
                            const unsigned long long fv = rw[i][j + dw];
                            ffma2(acc[i * 2 + j][0], fv, w.x);
                            ffma2(acc[i * 2 + j][1], fv, w.y);
                        }
                    }
                }
                // rotate window: bring in row (2pr + dh + 2)
                if (dh < 2) {
                    #pragma unroll
                    for (int wc = 0; wc < 4; ++wc) rw[0][wc] = rw[1][wc];
                    const int base = (2 * pr + dh + 2) * FCP + 2 * pc;
                    #pragma unroll
                    for (int wc = 0; wc < 4; ++wc)
                        rw[1][wc] = pack2(fpl[base + wc]);
                }
            }
        }
        __syncthreads();   // conv(c) done reading buf before featgen(c+2)
    }

    // ---- write out: 2 rows x 2 cols x 4 oc per thread, float2 over cols ----
    const int gh0 = th0 + 2 * pr;
    const int gw0 = tw0 + 2 * pc;
    #pragma unroll
    for (int i = 0; i < 2; ++i) {
        #pragma unroll
        for (int q = 0; q < 2; ++q) {
            const int oc = ocg * 4 + 2 * q;
            float l0, h0, l1, h1;
            unpack2(acc[i * 2 + 0][q], l0, h0);
            unpack2(acc[i * 2 + 1][q], l1, h1);
            float2* p0 = reinterpret_cast<float2*>(
                &out[((b * COUT + oc + 0) * HH + gh0 + i) * WW + gw0]);
            float2* p1 = reinterpret_cast<float2*>(
                &out[((b * COUT + oc + 1) * HH + gh0 + i) * WW + gw0]);
            *p0 = make_float2(l0, l1);
            *p1 = make_float2(h0, h1);
        }
    }
}

extern "C" void kernel_launch(void* const* d_in, const int* in_sizes, int n_in,
                              void* d_out, int out_size) {
    const float* x   = (const float*)d_in[0];
    const float* bw  = (const float*)d_in[1];
    const float* sw  = (const float*)d_in[2];
    const float* ss  = (const float*)d_in[3];
    float* out       = (float*)d_out;

    kan_fuse_kernel<<<(CIN * WCHUNK + 511) / 512, 512>>>(bw, sw, ss);

    // Maximize smem carveout so 7 CTAs/SM (29.4 KB each) are resident.
    cudaFuncSetAttribute(kan_conv_kernel,
                         cudaFuncAttributePreferredSharedMemoryCarveout, 100);

    dim3 grid(NTILES, BB);   // 64 tiles x 16 batches = 1024 CTAs x 128 thr
    kan_conv_kernel<<<grid, THREADS>>>(x, out);
}

// round 17
// speedup vs baseline: 1.0059x; 1.0059x over previous
#include <cuda_runtime.h>
#include <cstdint>

// Problem constants
#define BB   16
#define CIN  8
#define COUT 32
#define HH   64
#define WW   64
#define K2   9
#define NC   8          // spline coefficients per feature
#define NF   9          // features per cin: silu + 8 spline bases
#define TILE 8
#define NTILES 64       // conv: 8x8 grid of 8x8 tiles
#define THREADS 128

// Conv-side smem feature layout (8x8 tile + halo)
#define FR    10                       // halo rows
#define FCR   10                       // real halo cols
#define FCP   12                       // padded col stride (conflict-free)
#define FPIX_S (FR * FCP)              // 120 floats per plane (stored)
#define SF_FLOATS (NF * FPIX_S)        // 1080
#define WCHUNK   (NF * K2 * COUT)      // 2592 floats per cin

// Storage-side feature tiles: 16x16 + halo (quadrant-loaded by conv)
#define NSTILES 16                     // 4x4 grid of 16x16 tiles
#define SFR   18
#define SFCR  18
#define SFCP  20
#define SFPIX_S (SFR * SFCP)           // 360
#define SFPIX_R (SFR * SFCR)           // 324
#define SSF_FLOATS (NF * SFPIX_S)      // 3240

// Flat prep decomposition
#define NSLICES   (BB * CIN * NSTILES)         // 2048
#define FEAT_WORK (NSLICES * SFPIX_R)          // 663552
#define PREP_T    256
#define NB_FEAT   (FEAT_WORK / PREP_T)         // 2592 (exact)
#define NB_FUSE   ((CIN * WCHUNK + PREP_T - 1) / PREP_T)  // 81

// Fused weights + 16x16-tiled feature images.
__device__ float g_fused[CIN * WCHUNK];
__device__ float g_feat_t[(size_t)NSLICES * SSF_FLOATS];   // ~26.5 MB

__device__ __forceinline__ float silu_f(float x) {
    return x / (1.0f + __expf(-x));
}

// Packed f32x2 FMA: one issue slot, two fp32 FMAs, bit-identical rounding.
__device__ __forceinline__ void ffma2(unsigned long long& d,
                                      unsigned long long a,
                                      unsigned long long b) {
    asm("fma.rn.f32x2 %0, %1, %2, %0;" : "+l"(d) : "l"(a), "l"(b));
}

__device__ __forceinline__ unsigned long long pack2(float v) {
    unsigned long long p;
    asm("mov.b64 %0, {%1, %1};" : "=l"(p) : "f"(v));
    return p;
}

__device__ __forceinline__ void unpack2(unsigned long long p, float& lo, float& hi) {
    asm("mov.b64 {%0, %1}, %2;" : "=f"(lo), "=f"(hi) : "l"(p));
}

__device__ __forceinline__ void cp_async16(uint32_t saddr, const void* gptr) {
    asm volatile("cp.async.cg.shared.global [%0], [%1], 16;"
                 :: "r"(saddr), "l"(gptr));
}

// De Boor-Cox recursion, degree 3, uniform knots t[j] = (j-3)*0.4 - 1.0.
// Uniform knots => denominators exactly k*h; divisions replaced by
// compile-time reciprocal multiplies (deviation ~1e-7, tolerance 1e-3).
__device__ __forceinline__ void bspline8(float x, float* __restrict__ out) {
    float t[12];
    #pragma unroll
    for (int j = 0; j < 12; ++j) t[j] = (float)(j - 3) * 0.4f - 1.0f;

    float b[11];
    #pragma unroll
    for (int j = 0; j < 11; ++j)
        b[j] = (x >= t[j] && x < t[j + 1]) ? 1.0f : 0.0f;

    #pragma unroll
    for (int k = 1; k <= 3; ++k) {
        const float inv = 1.0f / (0.4f * (float)k);
        #pragma unroll
        for (int j = 0; j < 10; ++j) {
            if (j < 11 - k) {
                b[j] = (x - t[j]) * inv * b[j]
                     + (t[j + k + 1] - x) * inv * b[j + 1];
            }
        }
    }
    #pragma unroll
    for (int s = 0; s < NC; ++s) out[s] = b[s];
}

// ---- Kernel A: weight fusing + 16x16-tiled feature precompute ----
__global__ void kan_prep_kernel(const float* __restrict__ x,
                                const float* __restrict__ base_w,
                                const float* __restrict__ spline_w,
                                const float* __restrict__ spline_s)
{
    if (blockIdx.x >= NB_FEAT) {
        const int i = (blockIdx.x - NB_FEAT) * PREP_T + threadIdx.x;
        if (i < CIN * WCHUNK) {
            const int oc  = i & (COUT - 1);
            const int tap = (i / COUT) % K2;
            const int f   = (i / (COUT * K2)) % NF;
            const int c   = i / WCHUNK;
            const int widx = (oc * CIN + c) * K2 + tap;
            float w;
            if (f == 0) w = base_w[widx];
            else        w = spline_w[widx * NC + (f - 1)] * spline_s[widx];
            g_fused[i] = w;
        }
        return;
    }

    const int idx = blockIdx.x * PREP_T + threadIdx.x;
    const int slice = idx / SFPIX_R;         // (b*CIN+c)*NSTILES + stile
    const int px    = idx - slice * SFPIX_R;
    const int bc    = slice >> 4;            // b*CIN + c
    const int stile = slice & 15;
    const int th0   = (stile >> 2) * 16;
    const int tw0   = (stile & 3) * 16;

    const int hr = px / SFCR;
    const int hc = px % SFCR;
    const int gh = th0 + hr - 1;
    const int gw = tw0 + hc - 1;
    float v = 0.0f;
    if (gh >= 0 && gh < HH && gw >= 0 && gw < WW)
        v = x[bc * (HH * WW) + gh * WW + gw];
    float bs[NC];
    bspline8(v, bs);

    float* dst = g_feat_t + (size_t)slice * SSF_FLOATS;
    const int o = hr * SFCP + hc;
    dst[o] = silu_f(v);
    #pragma unroll
    for (int s = 0; s < NC; ++s)
        dst[(s + 1) * SFPIX_S + o] = bs[s];
}

// ---- Kernel B: main conv.
// 1024 CTAs x 128 threads -> 8 CTAs/SM (18.6 KB smem, <=63 regs), one wave.
// Thread: ocg = tid >> 4 (8 groups of 4 oc); pxb = tid & 15 -> 2x2 pixel
// block: pr = pxb>>2, pc = pxb&3. Per tap: 1 LDS.128 feeds 8 FFMA2.
// Weights: SINGLE buffer (same for all CTAs), cp.async per cin, arrival
// hidden by the 7 other resident CTAs. Features: double buffer, one cin
// ahead, loaded as the 8x8 quadrant of the stored 16x16 tile images.
__global__ void __launch_bounds__(THREADS, 8)
kan_conv_kernel(float* __restrict__ out)
{
    __shared__ __align__(16) float sF[2][SF_FLOATS];
    __shared__ __align__(16) float sW[WCHUNK];

    const int tid  = threadIdx.x;
    const int tile = blockIdx.x;      // 0..63
    const int b    = blockIdx.y;      // 0..15
    const int tr   = tile >> 3;       // 0..7
    const int tc   = tile & 7;        // 0..7
    const int th0  = tr * TILE;
    const int tw0  = tc * TILE;
    const int stile = (tr >> 1) * 4 + (tc >> 1);   // stored 16x16 tile
    const int qr   = (tr & 1) * 8;    // quadrant origin in stored tile
    const int qc   = (tc & 1) * 8;

    const int ocg = tid >> 4;         // 0..7
    const int pxb = tid & 15;
    const int pr  = pxb >> 2;         // 0..3 -> rows 2pr, 2pr+1
    const int pc  = pxb & 3;          // 0..3 -> cols 2pc, 2pc+1

    // Quadrant feature prefetch: 9 planes x 10 rows x 3 x 16B chunks = 270.
    auto prefetch_f = [&](int c, int bufIdx) {
        const float* src = g_feat_t +
            ((size_t)((b * CIN + c) * NSTILES + stile)) * SSF_FLOATS;
        const uint32_t fdst =
            (uint32_t)__cvta_generic_to_shared(&sF[bufIdx][0]);
        #pragma unroll
        for (int k = 0; k < 3; ++k) {
            const int i = tid + k * THREADS;
            if (i < 270) {
                const int f   = i / 30;
                const int rem = i - f * 30;
                const int row = rem / 3;
                const int ch  = rem - row * 3;
                const int so  = f * SFPIX_S + (qr + row) * SFCP + qc + ch * 4;
                const int dof = f * FPIX_S + row * FCP + ch * 4;
                cp_async16(fdst + dof * 4, src + so);
            }
        }
        asm volatile("cp.async.commit_group;");
    };
    auto prefetch_w = [&](int c) {
        const float4* wsrc =
            reinterpret_cast<const float4*>(g_fused + c * WCHUNK);
        const uint32_t wdst = (uint32_t)__cvta_generic_to_shared(&sW[0]);
        #pragma unroll
        for (int k = 0; k < 6; ++k) {
            const int i = tid + k * THREADS;
            if (i < WCHUNK / 4)                 // 648
                cp_async16(wdst + i * 16, wsrc + i);
        }
        asm volatile("cp.async.commit_group;");
    };

    // Accumulators: 4 px x 4 oc = 16 floats as 8 packed f32x2.
    unsigned long long acc[4][2];
    #pragma unroll
    for (int p = 0; p < 4; ++p) { acc[p][0] = 0ULL; acc[p][1] = 0ULL; }

    prefetch_f(0, 0);                  // group: feat(0)

    for (int c = 0; c < CIN; ++c) {
        const int buf = c & 1;

        prefetch_w(c);                 // group: weights(c)  (sW free: barrier)
        if (c < CIN - 1) {
            prefetch_f(c + 1, 1 - buf);   // group: feat(c+1)
            asm volatile("cp.async.wait_group 1;");  // feat(c)+weights(c) done
        } else {
            asm volatile("cp.async.wait_group 0;");
        }
        __syncthreads();   // staged data visible; prev readers done

        const float* __restrict__ sFb = sF[buf];

        #pragma unroll 3
        for (int f = 0; f < NF; ++f) {
            const float* fpl = sFb + f * FPIX_S;

            // rolling window rows: rw[0] = row (2pr+dh), rw[1] = next row
            unsigned long long rw[2][4];
            #pragma unroll
            for (int k = 0; k < 2; ++k) {
                const int base = (2 * pr + k) * FCP + 2 * pc;
                #pragma unroll
                for (int wc = 0; wc < 4; ++wc)
                    rw[k][wc] = pack2(fpl[base + wc]);
            }

            const float* wbase = sW + (f * K2) * COUT + ocg * 4;

            #pragma unroll
            for (int dh = 0; dh < 3; ++dh) {
                #pragma unroll
                for (int dw = 0; dw < 3; ++dw) {
                    const int tap = dh * 3 + dw;
                    const ulonglong2 w = *reinterpret_cast<const ulonglong2*>(
                        wbase + tap * COUT);
                    #pragma unroll
                    for (int i = 0; i < 2; ++i) {
                        #pragma unroll
                        for (int j = 0; j < 2; ++j) {
                            const unsigned long long fv = rw[i][j + dw];
                            ffma2(acc[i * 2 + j][0], fv, w.x);
                            ffma2(acc[i * 2 + j][1], fv, w.y);
                        }
                    }
                }
                // rotate window: bring in row (2pr + dh + 2)
                if (dh < 2) {
                    #pragma unroll
                    for (int wc = 0; wc < 4; ++wc) rw[0][wc] = rw[1][wc];
                    const int base = (2 * pr + dh + 2) * FCP + 2 * pc;
                    #pragma unroll
                    for (int wc = 0; wc < 4; ++wc)
                        rw[1][wc] = pack2(fpl[base + wc]);
                }
            }
        }
        __syncthreads();   // conv(c) done with sW/sF[buf] before next writes
    }

    // ---- write out: 2 rows x 2 cols x 4 oc per thread, float2 over cols ----
    const int gh0 = th0 + 2 * pr;
    const int gw0 = tw0 + 2 * pc;
    #pragma unroll
    for (int i = 0; i < 2; ++i) {
        #pragma unroll
        for (int q = 0; q < 2; ++q) {
            const int oc = ocg * 4 + 2 * q;
            float l0, h0, l1, h1;
            unpack2(acc[i * 2 + 0][q], l0, h0);
            unpack2(acc[i * 2 + 1][q], l1, h1);
            float2* p0 = reinterpret_cast<float2*>(
                &out[((b * COUT + oc + 0) * HH + gh0 + i) * WW + gw0]);
            float2* p1 = reinterpret_cast<float2*>(
                &out[((b * COUT + oc + 1) * HH + gh0 + i) * WW + gw0]);
            *p0 = make_float2(l0, l1);
            *p1 = make_float2(h0, h1);
        }
    }
}

extern "C" void kernel_launch(void* const* d_in, const int* in_sizes, int n_in,
                              void* d_out, int out_size) {
    const float* x   = (const float*)d_in[0];
    const float* bw  = (const float*)d_in[1];
    const float* sw  = (const float*)d_in[2];
    const float* ss  = (const float*)d_in[3];
    float* out       = (float*)d_out;

    // One flat prep launch: featgen blocks + fuse blocks.
    kan_prep_kernel<<<NB_FEAT + NB_FUSE, PREP_T>>>(x, bw, sw, ss);

    cudaFuncSetAttribute(kan_conv_kernel,
                         cudaFuncAttributePreferredSharedMemoryCarveout, 100);

    dim3 grid(NTILES, BB);   // 64 tiles x 16 batches = 1024 CTAs x 128 thr
    kan_conv_kernel<<<grid, THREADS>>>(out);
}